// round 16
// baseline (speedup 1.0000x reference)
#include <cuda_runtime.h>
#include <cuda_fp16.h>
#include <stdint.h>

#define NPIX 9216
#define DIMK 32
#define FELEMS (DIMK*NPIX)
#define JT 128
#define TI 128
#define ISPLIT 2
#define IRANGE (NPIX/ISPLIT)   // 4608
#define NCHG 18                // chunks per parity group (36 per split / 2)
#define NCTA 144
#define SLOTS (ISPLIT*2)       // split*2 + group = 4
#define SCALE 4.328085122666891f   // 3 * log2(e)

// device scratch (no allocations allowed)
__device__ __half g_xq[NPIX*DIMK];   // [pixel][d], scaled by 3*log2e (A1 operand)
__device__ __half g_xp[NPIX*DIMK];   // [pixel][d], unscaled (B1 operand)
__device__ __half g_xa[DIMK*NPIX];   // [d][pixel], unscaled (B2 operand)
__device__ float g_xf[FELEMS];       // current x fp32, d-major
__device__ float g_pv[SLOTS*FELEMS]; // partial v [slot][d][j]
__device__ float g_ps[SLOTS*NPIX];   // partial s [slot][j]

// grid barrier state (self-resetting across launches)
__device__ unsigned g_cnt = 0;
__device__ volatile unsigned g_gen = 0;

__device__ __forceinline__ void gsync() {
    __syncthreads();
    if (threadIdx.x == 0) {
        unsigned my = g_gen;
        __threadfence();
        if (atomicAdd(&g_cnt, 1) == NCTA - 1) {
            g_cnt = 0;
            __threadfence();
            g_gen = my + 1;
        } else {
            while (g_gen == my) {}
            __threadfence();
        }
    }
    __syncthreads();
}

__device__ __forceinline__ uint32_t smem_u32(const void* p) {
    uint32_t a;
    asm("{ .reg .u64 t; cvta.to.shared.u64 t, %1; cvt.u32.u64 %0, t; }" : "=r"(a) : "l"(p));
    return a;
}

#define LDSM4(r0,r1,r2,r3,addr) \
    asm volatile("ldmatrix.sync.aligned.m8n8.x4.shared.b16 {%0,%1,%2,%3}, [%4];" \
        : "=r"(r0),"=r"(r1),"=r"(r2),"=r"(r3) : "r"(addr))

#define MMA16816(C, A, b0, b1) \
    asm volatile("mma.sync.aligned.m16n8k16.row.col.f32.f16.f16.f32 " \
        "{%0,%1,%2,%3}, {%4,%5,%6,%7}, {%8,%9}, {%0,%1,%2,%3};" \
        : "+f"((C)[0]), "+f"((C)[1]), "+f"((C)[2]), "+f"((C)[3]) \
        : "r"((A)[0]), "r"((A)[1]), "r"((A)[2]), "r"((A)[3]), "r"(b0), "r"(b1))

__device__ __forceinline__ void cp16cg(uint32_t dst, const void* src) {
    asm volatile("cp.async.cg.shared.global [%0], [%1], 16;"
        :: "r"(dst), "l"(__cvta_generic_to_global(src)) : "memory");
}
__device__ __forceinline__ uint32_t pkh2(float lo, float hi) {
    uint32_t r; asm("cvt.rn.f16x2.f32 %0, %1, %2;" : "=r"(r) : "f"(hi), "f"(lo)); return r;
}
__device__ __forceinline__ uint32_t ex2h2(uint32_t x) {
    uint32_t r; asm("ex2.approx.f16x2 %0, %1;" : "=r"(r) : "r"(x)); return r;
}
__device__ __forceinline__ void barg(int g) {
    asm volatile("bar.sync %0, 128;" :: "r"(g + 1) : "memory");
}

// smem: 4 regions (2 groups x 2 bufs); region = Xi(128r x 80B) + Xd(40r x 272B)
#define SXI_STRIDE 80
#define SXD_STRIDE 272
#define SXI_BUF (TI*SXI_STRIDE)          // 10240
#define SXD_BUF (40*SXD_STRIDE)          // 10880
#define RBUF (SXI_BUF+SXD_BUF)           // 21120
#define SMEM_BYTES (4*RBUF)              // 84480 (dynamic)

__device__ __forceinline__ void main_phase(uint32_t sbase, int jb, int split)
{
    const int tid = threadIdx.x;
    const int g = tid >> 7;              // chunk-parity group 0/1
    const int wg = (tid >> 5) & 3;       // warp within group
    const int l = tid & 31;
    const int wt = tid & 127;
    const int i0b = split * IRANGE;
    const int slot = split * 2 + g;

    // A1 fragments (g_xq mutated by cvt phase -> L2 loads)
    const uint32_t* xq32 = (const uint32_t*)g_xq;
    uint32_t a1f[2][2][4];
#pragma unroll
    for (int jblk = 0; jblk < 2; jblk++) {
        const int row0 = jb + wg * 32 + jblk * 16 + (l >> 2);
#pragma unroll
        for (int ks = 0; ks < 2; ks++) {
            a1f[jblk][ks][0] = __ldcg(&xq32[row0 * 16 + ks * 8 + (l & 3)]);
            a1f[jblk][ks][1] = __ldcg(&xq32[(row0 + 8) * 16 + ks * 8 + (l & 3)]);
            a1f[jblk][ks][2] = __ldcg(&xq32[row0 * 16 + ks * 8 + 4 + (l & 3)]);
            a1f[jblk][ks][3] = __ldcg(&xq32[(row0 + 8) * 16 + ks * 8 + 4 + (l & 3)]);
        }
    }

    float vf[2][5][4];
#pragma unroll
    for (int jblk = 0; jblk < 2; jblk++)
#pragma unroll
        for (int n = 0; n < 5; n++)
#pragma unroll
            for (int q = 0; q < 4; q++) vf[jblk][n][q] = 0.0f;

    const char* gxp = (const char*)g_xp;
    const char* gxa = (const char*)g_xa;

    // region for (group, buf): base + (g*2 + b)*RBUF
#define REGION(b_) (sbase + (uint32_t)((g * 2 + (b_)) * RBUF))

    // fill by 128 group threads: Xi 128r x 4x16B (512) + Xd 32r x 16x16B (512)
#define ISSUE(cc_) do { \
        int c_ = 2 * (cc_) + g; int i0_ = i0b + c_ * TI; \
        uint32_t rb_ = REGION((cc_) & 1); \
        _Pragma("unroll") \
        for (int k_ = 0; k_ < 4; k_++) { \
            int idx_ = wt + k_ * 128; \
            int xr_ = idx_ >> 2, xc_ = idx_ & 3; \
            cp16cg(rb_ + xr_ * SXI_STRIDE + xc_ * 16, \
                   gxp + (size_t)(i0_ + xr_) * 64 + xc_ * 16); \
            int dr_ = idx_ >> 4, dc_ = idx_ & 15; \
            cp16cg(rb_ + SXI_BUF + dr_ * SXD_STRIDE + dc_ * 16, \
                   gxa + ((size_t)dr_ * NPIX + i0_) * 2 + dc_ * 16); \
        } \
        asm volatile("cp.async.commit_group;" ::: "memory"); \
    } while (0)

    ISSUE(0);

    for (int cc = 0; cc < NCHG; cc++) {
        asm volatile("cp.async.wait_group 0;" ::: "memory");
        barg(g);
        if (cc + 1 < NCHG) ISSUE(cc + 1);

        const uint32_t pXi = REGION(cc & 1);
        const uint32_t pXd = pXi + SXI_BUF;

        // p-quarter: hoist ALL LDSMs, then MMA1+exp chains, then MMA2s
#pragma unroll
        for (int p = 0; p < 4; p++) {
            uint32_t xf[4][4];   // Xi fragments for nn=0..3
#pragma unroll
            for (int nn = 0; nn < 4; nn++) {
                int n = p * 4 + nn;
                uint32_t addr = pXi + (n * 8 + (l & 7)) * SXI_STRIDE + (l >> 3) * 16;
                LDSM4(xf[nn][0], xf[nn][1], xf[nn][2], xf[nn][3], addr);
            }
            uint32_t df[5][4];   // Xd fragments for nd=0..4
#pragma unroll
            for (int nd = 0; nd < 5; nd++) {
                uint32_t addr = pXd + (nd * 8 + (l & 7)) * SXD_STRIDE + p * 64 + (l >> 3) * 16;
                LDSM4(df[nd][0], df[nd][1], df[nd][2], df[nd][3], addr);
            }

            uint32_t a2f[2][2][4];   // [jblk][kk][4]
#pragma unroll
            for (int nn = 0; nn < 4; nn++) {
                int kk = nn >> 1;
#pragma unroll
                for (int jblk = 0; jblk < 2; jblk++) {
                    float C[4];
                    C[0] = 0.f; C[1] = 0.f; C[2] = 0.f; C[3] = 0.f;
                    MMA16816(C, a1f[jblk][0], xf[nn][0], xf[nn][1]);
                    MMA16816(C, a1f[jblk][1], xf[nn][2], xf[nn][3]);
                    uint32_t e01 = ex2h2(pkh2(C[0], C[1]));
                    uint32_t e23 = ex2h2(pkh2(C[2], C[3]));
                    if ((nn & 1) == 0) { a2f[jblk][kk][0] = e01; a2f[jblk][kk][1] = e23; }
                    else              { a2f[jblk][kk][2] = e01; a2f[jblk][kk][3] = e23; }
                }
            }
#pragma unroll
            for (int nd = 0; nd < 5; nd++) {
#pragma unroll
                for (int jblk = 0; jblk < 2; jblk++) {
                    MMA16816(vf[jblk][nd], a2f[jblk][0], df[nd][0], df[nd][1]);
                    MMA16816(vf[jblk][nd], a2f[jblk][1], df[nd][2], df[nd][3]);
                }
            }
        }
    }
#undef ISSUE
#undef REGION

    // ---- s from ones-column (col 32 => nd=4, (l&3)==0, q in {0,2}) ----
#pragma unroll
    for (int jblk = 0; jblk < 2; jblk++) {
        if ((l & 3) == 0) {
            int j0 = jb + wg * 32 + jblk * 16 + (l >> 2);
            g_ps[slot * NPIX + j0] = vf[jblk][4][0];
            g_ps[slot * NPIX + j0 + 8] = vf[jblk][4][2];
        }
    }
    // ---- V writeback ----
#pragma unroll
    for (int jblk = 0; jblk < 2; jblk++)
#pragma unroll
        for (int nd = 0; nd < 4; nd++)
#pragma unroll
            for (int q = 0; q < 4; q++) {
                int d = nd * 8 + (l & 3) * 2 + (q & 1);
                int j = jb + wg * 32 + jblk * 16 + (l >> 2) + ((q >= 2) ? 8 : 0);
                g_pv[(slot * DIMK + d) * NPIX + j] = vf[jblk][nd][q];
            }
}

// it == -1: prep. it >= 0: combine partials + update + outputs.
// 144 CTAs x 256 thr: each CTA covers 64 j's x all 32 d's.
__device__ __forceinline__ void cvt_phase(int it, const float* __restrict__ x,
                                          float* __restrict__ out, int bid)
{
    const int tid = threadIdx.x;
    const int j = bid * 64 + (tid & 63);
    const int dg = tid >> 6;            // 0..3 -> d in [dg*8, dg*8+8)
    float inv = 0.0f;
    if (it >= 0) {
        float s = 0.0f;
#pragma unroll
        for (int ib = 0; ib < SLOTS; ib++) s += __ldcg(&g_ps[ib * NPIX + j]);
        inv = 0.5f / s;
    }
    float v[8];
#pragma unroll
    for (int q = 0; q < 8; q++) {
        int d = dg * 8 + q;
        float xo = (it <= 0) ? x[d * NPIX + j] : g_xf[d * NPIX + j];
        if (it < 0) {
            v[q] = xo;
        } else {
            float pv = 0.0f;
#pragma unroll
            for (int ib = 0; ib < SLOTS; ib++)
                pv += __ldcg(&g_pv[(ib * DIMK + d) * NPIX + j]);
            float val = pv * inv + 0.5f * xo;
            v[q] = val;
            out[(1 + it) * FELEMS + d * NPIX + j] = val;
            if (it == 2) out[d * NPIX + j] = val;
            if (it < 2) g_xf[d * NPIX + j] = val;
        }
        if (it < 2) g_xa[d * NPIX + j] = __float2half_rn(v[q]);
    }
    if (it < 2) {
        uint32_t* xp32 = (uint32_t*)g_xp;
        uint32_t* xq32 = (uint32_t*)g_xq;
#pragma unroll
        for (int q = 0; q < 8; q += 2) {
            int d = dg * 8 + q;
            xp32[j * 16 + d / 2] = pkh2(v[q], v[q + 1]);
            xq32[j * 16 + d / 2] = pkh2(v[q] * SCALE, v[q + 1] * SCALE);
        }
    }
}

__global__ void __launch_bounds__(256, 1) ms_all(const float* __restrict__ x,
                                                float* __restrict__ out)
{
    extern __shared__ __align__(128) unsigned char smem_dyn[];
    const uint32_t sbase = smem_u32(smem_dyn);
    const int bid = blockIdx.x;
    const int tid = threadIdx.x;
    const int jb = (bid >> 1) * JT;      // 72 j-tiles
    const int split = bid & 1;           // 2 i-splits

    // static Xd rows 32..39 in all 4 regions: row 32 = ones, rows 33..39 = zeros
    for (int idx = tid; idx < 4 * 8 * 68; idx += 256) {
        int reg_ = idx / (8 * 68), rem = idx % (8 * 68);
        int rr = rem / 68, cw = rem % 68;
        uint32_t v = (rr == 0) ? 0x3C003C00u : 0u;
        *(uint32_t*)(smem_dyn + reg_ * RBUF + SXI_BUF + (32 + rr) * SXD_STRIDE + cw * 4) = v;
    }

    cvt_phase(-1, x, out, bid);   // prep
    gsync();
    for (int it = 0; it < 3; it++) {
        main_phase(sbase, jb, split);
        gsync();
        cvt_phase(it, x, out, bid);
        if (it < 2) gsync();
    }
}

extern "C" void kernel_launch(void* const* d_in, const int* in_sizes, int n_in,
                              void* d_out, int out_size)
{
    const float* x = (const float*)d_in[0];
    float* out = (float*)d_out;
    cudaFuncSetAttribute(ms_all, cudaFuncAttributeMaxDynamicSharedMemorySize, SMEM_BYTES);
    ms_all<<<NCTA, 256, SMEM_BYTES>>>(x, out);
}

// round 17
// speedup vs baseline: 1.1506x; 1.1506x over previous
#include <cuda_runtime.h>
#include <cuda_fp16.h>
#include <stdint.h>

#define NPIX 9216
#define DIMK 32
#define FELEMS (DIMK*NPIX)
#define JT 256
#define TI 128
#define ISPLIT 8
#define IRANGE (NPIX/ISPLIT)   // 1152
#define NCH (IRANGE/TI)        // 9
#define NCTA 288
#define SLOTS ISPLIT
#define SCALE 4.328085122666891f   // 3 * log2(e)

// device scratch (no allocations allowed)
__device__ __half g_xq[NPIX*DIMK];   // [pixel][d], scaled by 3*log2e (A1 operand)
__device__ __half g_xp[NPIX*DIMK];   // [pixel][d], unscaled (B1 operand)
__device__ __half g_xa[DIMK*NPIX];   // [d][pixel], unscaled (B2 operand)
__device__ float g_xf[FELEMS];       // current x fp32, d-major
__device__ float g_pv[SLOTS*FELEMS]; // partial v [slot][d][j]
__device__ float g_ps[SLOTS*NPIX];   // partial s [slot][j]

// grid barrier state (self-resetting across launches)
__device__ unsigned g_cnt = 0;
__device__ volatile unsigned g_gen = 0;

__device__ __forceinline__ void gsync() {
    __syncthreads();
    if (threadIdx.x == 0) {
        unsigned my = g_gen;
        __threadfence();
        if (atomicAdd(&g_cnt, 1) == NCTA - 1) {
            g_cnt = 0;
            __threadfence();
            g_gen = my + 1;
        } else {
            while (g_gen == my) {}
            __threadfence();
        }
    }
    __syncthreads();
}

__device__ __forceinline__ uint32_t smem_u32(const void* p) {
    uint32_t a;
    asm("{ .reg .u64 t; cvta.to.shared.u64 t, %1; cvt.u32.u64 %0, t; }" : "=r"(a) : "l"(p));
    return a;
}

#define LDSM4(r0,r1,r2,r3,addr) \
    asm volatile("ldmatrix.sync.aligned.m8n8.x4.shared.b16 {%0,%1,%2,%3}, [%4];" \
        : "=r"(r0),"=r"(r1),"=r"(r2),"=r"(r3) : "r"(addr))

// f32-accum MMA (for MMA2 / V accumulation)
#define MMA16816(C, A, b0, b1) \
    asm volatile("mma.sync.aligned.m16n8k16.row.col.f32.f16.f16.f32 " \
        "{%0,%1,%2,%3}, {%4,%5,%6,%7}, {%8,%9}, {%0,%1,%2,%3};" \
        : "+f"((C)[0]), "+f"((C)[1]), "+f"((C)[2]), "+f"((C)[3]) \
        : "r"((A)[0]), "r"((A)[1]), "r"((A)[2]), "r"((A)[3]), "r"(b0), "r"(b1))

// f16-accum MMA (for MMA1 / S): C = 2 packed f16x2 regs, layout == packed A-frag pairs
#define MMA16816H(C2, A, b0, b1) \
    asm volatile("mma.sync.aligned.m16n8k16.row.col.f16.f16.f16.f16 " \
        "{%0,%1}, {%2,%3,%4,%5}, {%6,%7}, {%0,%1};" \
        : "+r"((C2)[0]), "+r"((C2)[1]) \
        : "r"((A)[0]), "r"((A)[1]), "r"((A)[2]), "r"((A)[3]), "r"(b0), "r"(b1))

__device__ __forceinline__ void cp16cg(uint32_t dst, const void* src) {
    asm volatile("cp.async.cg.shared.global [%0], [%1], 16;"
        :: "r"(dst), "l"(__cvta_generic_to_global(src)) : "memory");
}
__device__ __forceinline__ uint32_t pkh2(float lo, float hi) {
    uint32_t r; asm("cvt.rn.f16x2.f32 %0, %1, %2;" : "=r"(r) : "f"(hi), "f"(lo)); return r;
}
__device__ __forceinline__ uint32_t ex2h2(uint32_t x) {
    uint32_t r; asm("ex2.approx.f16x2 %0, %1;" : "=r"(r) : "r"(x)); return r;
}

// smem: 2 regions, each = Xi(128 rows x 80B) + Xd(40 rows x 272B)
#define SXI_STRIDE 80
#define SXD_STRIDE 272
#define SXI_BUF (TI*SXI_STRIDE)          // 10240
#define SXD_BUF (40*SXD_STRIDE)          // 10880
#define RBUF (SXI_BUF+SXD_BUF)           // 21120
#define SMEM_BYTES (2*RBUF)              // 42240

struct SmemT { unsigned char buf[SMEM_BYTES]; };

__device__ __forceinline__ void main_phase(SmemT* sm, int jb, int split)
{
    const uint32_t sbase = smem_u32(sm->buf);
    const int tid = threadIdx.x;
    const int w = tid >> 5;
    const int l = tid & 31;
    const int i0b = split * IRANGE;

    // A1 fragments (g_xq mutated by cvt phase -> L2 loads)
    const uint32_t* xq32 = (const uint32_t*)g_xq;
    uint32_t a1f[2][2][4];
#pragma unroll
    for (int jblk = 0; jblk < 2; jblk++) {
        const int row0 = jb + w * 32 + jblk * 16 + (l >> 2);
#pragma unroll
        for (int ks = 0; ks < 2; ks++) {
            a1f[jblk][ks][0] = __ldcg(&xq32[row0 * 16 + ks * 8 + (l & 3)]);
            a1f[jblk][ks][1] = __ldcg(&xq32[(row0 + 8) * 16 + ks * 8 + (l & 3)]);
            a1f[jblk][ks][2] = __ldcg(&xq32[row0 * 16 + ks * 8 + 4 + (l & 3)]);
            a1f[jblk][ks][3] = __ldcg(&xq32[(row0 + 8) * 16 + ks * 8 + 4 + (l & 3)]);
        }
    }

    float vf[2][5][4];
#pragma unroll
    for (int jblk = 0; jblk < 2; jblk++)
#pragma unroll
        for (int n = 0; n < 5; n++)
#pragma unroll
            for (int q = 0; q < 4; q++) vf[jblk][n][q] = 0.0f;

    const char* gxp = (const char*)g_xp;
    const char* gxa = (const char*)g_xa;

    // fill: Xi 128 rows x 4 x 16B = 512 chunks; Xd rows 0..31 x 16 x 16B = 512 chunks
#define ISSUE(c_) do { \
        int i0_ = i0b + (c_) * TI; \
        uint32_t rb_ = sbase + ((c_) & 1) * RBUF; \
        _Pragma("unroll") \
        for (int k_ = 0; k_ < 2; k_++) { \
            int idx_ = tid + k_ * 256; \
            int xr_ = idx_ >> 2, xc_ = idx_ & 3; \
            cp16cg(rb_ + xr_ * SXI_STRIDE + xc_ * 16, \
                   gxp + (size_t)(i0_ + xr_) * 64 + xc_ * 16); \
            int dr_ = idx_ >> 4, dc_ = idx_ & 15; \
            cp16cg(rb_ + SXI_BUF + dr_ * SXD_STRIDE + dc_ * 16, \
                   gxa + ((size_t)dr_ * NPIX + i0_) * 2 + dc_ * 16); \
        } \
        asm volatile("cp.async.commit_group;" ::: "memory"); \
    } while (0)

    ISSUE(0);

    for (int c = 0; c < NCH; c++) {
        asm volatile("cp.async.wait_group 0;" ::: "memory");
        __syncthreads();
        if (c + 1 < NCH) ISSUE(c + 1);

        const uint32_t pXi = sbase + (c & 1) * RBUF;
        const uint32_t pXd = pXi + SXI_BUF;

        // p-quarter loop: MMA1(f16 accum)+exp for 32 i's, then their MMA2s
#pragma unroll
        for (int p = 0; p < 4; p++) {
            uint32_t a2f[2][2][4];   // [jblk][kk within quarter][4]
#pragma unroll
            for (int nn = 0; nn < 4; nn++) {
                int n = p * 4 + nn;
                uint32_t q0, q1, q2, q3;
                uint32_t addr = pXi + (n * 8 + (l & 7)) * SXI_STRIDE + (l >> 3) * 16;
                LDSM4(q0, q1, q2, q3, addr);
                int kk = nn >> 1;
#pragma unroll
                for (int jblk = 0; jblk < 2; jblk++) {
                    uint32_t C2[2];
                    C2[0] = 0u; C2[1] = 0u;
                    MMA16816H(C2, a1f[jblk][0], q0, q1);
                    MMA16816H(C2, a1f[jblk][1], q2, q3);
                    // C2[0]=(c0,c1) row r, C2[1]=(c2,c3) row r+8 -> exp directly
                    uint32_t e01 = ex2h2(C2[0]);
                    uint32_t e23 = ex2h2(C2[1]);
                    if ((nn & 1) == 0) { a2f[jblk][kk][0] = e01; a2f[jblk][kk][1] = e23; }
                    else              { a2f[jblk][kk][2] = e01; a2f[jblk][kk][3] = e23; }
                }
            }
            // MMA2 for this quarter: V[j, d(40)] += P(:, 32p..32p+32) * Xd
#pragma unroll
            for (int nd = 0; nd < 5; nd++) {
                uint32_t q0, q1, q2, q3;
                uint32_t addr = pXd + (nd * 8 + (l & 7)) * SXD_STRIDE + p * 64 + (l >> 3) * 16;
                LDSM4(q0, q1, q2, q3, addr);
#pragma unroll
                for (int jblk = 0; jblk < 2; jblk++) {
                    MMA16816(vf[jblk][nd], a2f[jblk][0], q0, q1);
                    MMA16816(vf[jblk][nd], a2f[jblk][1], q2, q3);
                }
            }
        }
    }
#undef ISSUE

    // ---- s from ones-column (col 32 => nd=4, (l&3)==0, q in {0,2}) ----
#pragma unroll
    for (int jblk = 0; jblk < 2; jblk++) {
        if ((l & 3) == 0) {
            int j0 = jb + w * 32 + jblk * 16 + (l >> 2);
            g_ps[split * NPIX + j0] = vf[jblk][4][0];
            g_ps[split * NPIX + j0 + 8] = vf[jblk][4][2];
        }
    }
    // ---- V writeback ----
#pragma unroll
    for (int jblk = 0; jblk < 2; jblk++)
#pragma unroll
        for (int nd = 0; nd < 4; nd++)
#pragma unroll
            for (int q = 0; q < 4; q++) {
                int d = nd * 8 + (l & 3) * 2 + (q & 1);
                int j = jb + w * 32 + jblk * 16 + (l >> 2) + ((q >= 2) ? 8 : 0);
                g_pv[(split * DIMK + d) * NPIX + j] = vf[jblk][nd][q];
            }
}

// it == -1: prep (convert input). it >= 0: combine partials + update + outputs.
__device__ __forceinline__ void cvt_phase(int it, const float* __restrict__ x,
                                          float* __restrict__ out, int bid)
{
    const int tid = threadIdx.x;
    const int j = bid * 32 + (tid & 31);
    const int dg = tid >> 5;            // 0..7 -> d in [dg*4, dg*4+4)
    float inv = 0.0f;
    if (it >= 0) {
        float s = 0.0f;
#pragma unroll
        for (int ib = 0; ib < SLOTS; ib++) s += __ldcg(&g_ps[ib * NPIX + j]);
        inv = 0.5f / s;
    }
    float v[4];
#pragma unroll
    for (int q = 0; q < 4; q++) {
        int d = dg * 4 + q;
        float xo = (it <= 0) ? x[d * NPIX + j] : g_xf[d * NPIX + j];
        if (it < 0) {
            v[q] = xo;
        } else {
            float pv = 0.0f;
#pragma unroll
            for (int ib = 0; ib < SLOTS; ib++)
                pv += __ldcg(&g_pv[(ib * DIMK + d) * NPIX + j]);
            float val = pv * inv + 0.5f * xo;
            v[q] = val;
            out[(1 + it) * FELEMS + d * NPIX + j] = val;
            if (it == 2) out[d * NPIX + j] = val;
            if (it < 2) g_xf[d * NPIX + j] = val;
        }
        if (it < 2) g_xa[d * NPIX + j] = __float2half_rn(v[q]);
    }
    if (it < 2) {
        uint32_t* xp32 = (uint32_t*)g_xp;
        uint32_t* xq32 = (uint32_t*)g_xq;
#pragma unroll
        for (int q = 0; q < 4; q += 2) {
            int d = dg * 4 + q;
            xp32[j * 16 + d / 2] = pkh2(v[q], v[q + 1]);
            xq32[j * 16 + d / 2] = pkh2(v[q] * SCALE, v[q + 1] * SCALE);
        }
    }
}

__global__ void __launch_bounds__(256, 2) ms_all(const float* __restrict__ x,
                                                float* __restrict__ out)
{
    __shared__ __align__(128) SmemT sm;
    const int bid = blockIdx.x;
    const int tid = threadIdx.x;
    const int jb = (bid >> 3) * JT;      // 36 j-tiles
    const int split = bid & 7;           // 8 i-splits

    // static Xd rows 32..39 in both regions: row 32 = ones, rows 33..39 = zeros
    for (int idx = tid; idx < 2 * 8 * 64; idx += 256) {
        int reg_ = idx >> 9, rem = idx & 511;
        int rr = rem >> 6, cw = rem & 63;
        uint32_t v = (rr == 0) ? 0x3C003C00u : 0u;
        *(uint32_t*)(sm.buf + reg_ * RBUF + SXI_BUF + (32 + rr) * SXD_STRIDE + cw * 4) = v;
    }

    cvt_phase(-1, x, out, bid);   // prep
    gsync();
    for (int it = 0; it < 3; it++) {
        main_phase(&sm, jb, split);
        gsync();
        cvt_phase(it, x, out, bid);
        if (it < 2) gsync();
    }
}

extern "C" void kernel_launch(void* const* d_in, const int* in_sizes, int n_in,
                              void* d_out, int out_size)
{
    const float* x = (const float*)d_in[0];
    float* out = (float*)d_out;
    ms_all<<<NCTA, 256>>>(x, out);
}